// round 2
// baseline (speedup 1.0000x reference)
#include <cuda_runtime.h>
#include <cstdint>

// Problem constants (fixed shapes per reference)
#define N_NODES 50000
#define N_EDGES 800000
// IN_CH = 128 (32 float4), OUT_CH = 128, K = 256 (64 float4)

// Scratch: neighbor-sum accumulator + degree counts (device globals, no allocs)
__device__ __align__(16) float4 g_neigh4[N_NODES * 32];
__device__ __align__(16) float  g_deg[((N_NODES + 3) / 4) * 4];
__device__ int g_ei_is64;   // 1 if edge_index is int64, 0 if int32

// ---------------------------------------------------------------------------
// Kernel 1: zero scratch + detect edge_index dtype.
// Probe: first 64 entries read as int64 are always in [0, N_NODES) when the
// buffer is genuinely int64; if it is really int32, the reinterpreted value
// is (lo | hi<<32) with hi a random node id -> out of range w.h.p.
// Probing only the first 64 int64 slots stays inside the buffer either way.
// ---------------------------------------------------------------------------
__global__ void __launch_bounds__(256) zero_kernel(const long long* __restrict__ ei) {
    int i = blockIdx.x * blockDim.x + threadIdx.x;
    if (i < N_NODES * 32) g_neigh4[i] = make_float4(0.f, 0.f, 0.f, 0.f);
    if (i < (N_NODES + 3) / 4)
        ((float4*)g_deg)[i] = make_float4(0.f, 0.f, 0.f, 0.f);
    if (i == 0) {
        int ok = 1;
        for (int k = 0; k < 64; k++) {
            long long v = ei[k];
            if (v < 0 || v >= N_NODES) { ok = 0; break; }
        }
        g_ei_is64 = ok;
    }
}

// ---------------------------------------------------------------------------
// Kernel 2: edge scatter. One warp per edge: 32 lanes x float4 = 128 floats.
// Gather x[src] (L2-resident), vector-RED into g_neigh4[dst], count degree.
// ---------------------------------------------------------------------------
__global__ void __launch_bounds__(256) scatter_kernel(
    const float4* __restrict__ x4,
    const long long* __restrict__ ei)   // [2, N_EDGES]; dtype per g_ei_is64
{
    int e = (blockIdx.x * blockDim.x + threadIdx.x) >> 5;
    int lane = threadIdx.x & 31;
    if (e >= N_EDGES) return;

    int s, d;
    if (g_ei_is64) {
        s = (int)__ldg(ei + e);
        d = (int)__ldg(ei + N_EDGES + e);
    } else {
        const int* ei32 = (const int*)ei;
        s = __ldg(ei32 + e);
        d = __ldg(ei32 + N_EDGES + e);
    }
    // Defensive: never fault on unexpected index content
    if ((unsigned)s >= N_NODES || (unsigned)d >= N_NODES) return;

    float4 v = __ldg(x4 + s * 32 + lane);

    unsigned long long p =
        (unsigned long long)__cvta_generic_to_global(g_neigh4 + d * 32 + lane);
    asm volatile("red.global.add.v4.f32 [%0], {%1,%2,%3,%4};"
                 :: "l"(p), "f"(v.x), "f"(v.y), "f"(v.z), "f"(v.w) : "memory");

    if (lane == 0) {
        unsigned long long pd =
            (unsigned long long)__cvta_generic_to_global(g_deg + d);
        asm volatile("red.global.add.f32 [%0], %1;" :: "l"(pd), "f"(1.0f) : "memory");
    }
}

// ---------------------------------------------------------------------------
// Kernel 3: fused [x | neigh/deg] @ W^T + b, then row L2-normalize.
// Block = 256 threads, 32 rows x 128 cols per block.
// Thread (cg = tid&7, rw = tid>>3) computes row rw, cols [cg*16, cg*16+16).
// W staged in smem [128 cols][64 float4-chunks] with chunk ^= colgrp XOR
// swizzle -> conflict-free 8-distinct-bank LDS.128 wavefronts.
// Packed fma.rn.f32x2 halves FFMA issue.
// ---------------------------------------------------------------------------
#define FMA2(acc, av, wv) \
    asm("fma.rn.f32x2 %0, %1, %2, %0;" : "+l"(acc) : "l"(av), "l"(wv))
#define UNPACK2(lo, hi, v) \
    asm("mov.b64 {%0,%1}, %2;" : "=f"(lo), "=f"(hi) : "l"(v))

__global__ void __launch_bounds__(256, 1) gemm_norm_kernel(
    const float4* __restrict__ x4,
    const float4* __restrict__ W4,     // [128][64] float4 row-major (W[c][k])
    const float*  __restrict__ bias,   // [128]
    float4*       __restrict__ out4)   // [N_NODES][32]
{
    extern __shared__ float4 sm[];
    float4* Ws = sm;            // 8192 float4 = 128 KB, swizzled
    float4* hs = sm + 8192;     // [32 rows][65 float4] (padded) = 33280 B

    const int tid  = threadIdx.x;
    const int base = blockIdx.x * 32;

    // Stage W with XOR swizzle: Ws[(c<<6) | (chunk ^ (c>>4))] = W[c][chunk]
    #pragma unroll
    for (int i = tid; i < 8192; i += 256) {
        int c = i >> 6, ch = i & 63;
        Ws[(c << 6) | (ch ^ (c >> 4))] = __ldg(W4 + i);
    }
    // Stage h = [x | neigh * 1/max(deg,1)] for 32 rows
    #pragma unroll
    for (int i = tid; i < 2048; i += 256) {
        int r = i >> 6, k4 = i & 63;
        int row = base + r;
        float4 v = make_float4(0.f, 0.f, 0.f, 0.f);
        if (row < N_NODES) {
            if (k4 < 32) {
                v = __ldg(x4 + row * 32 + k4);
            } else {
                v = g_neigh4[row * 32 + (k4 - 32)];
                float s = 1.0f / fmaxf(g_deg[row], 1.0f);
                v.x *= s; v.y *= s; v.z *= s; v.w *= s;
            }
        }
        hs[r * 65 + k4] = v;
    }
    __syncthreads();

    const int cg = tid & 7;
    const int rw = tid >> 3;

    // Two f32x2 partial accumulators per output col (4 fp32 partials/col)
    unsigned long long accA[16], accB[16];
    #pragma unroll
    for (int j = 0; j < 16; j++) { accA[j] = 0ull; accB[j] = 0ull; }

    const ulonglong2* WsU = (const ulonglong2*)Ws;
    const ulonglong2* hsU = (const ulonglong2*)hs;

    #pragma unroll 4
    for (int k4 = 0; k4 < 64; ++k4) {
        ulonglong2 a = hsU[rw * 65 + k4];        // h[row][4k..4k+3] as 2x f32x2
        int wbase = (cg << 10) | (k4 ^ cg);      // (cg*16)<<6 | swizzled chunk
        #pragma unroll
        for (int j = 0; j < 16; j++) {
            ulonglong2 w = WsU[wbase + (j << 6)];
            FMA2(accA[j], a.x, w.x);             // k, k+1
            FMA2(accB[j], a.y, w.y);             // k+2, k+3
        }
    }

    // Epilogue: reduce partials, add bias, row L2-norm via 8-lane shfl reduce
    float o[16];
    float ss = 0.f;
    #pragma unroll
    for (int j = 0; j < 16; j++) {
        float a0, a1, b0, b1;
        UNPACK2(a0, a1, accA[j]);
        UNPACK2(b0, b1, accB[j]);
        float v = (a0 + a1) + (b0 + b1) + __ldg(bias + cg * 16 + j);
        o[j] = v;
        ss += v * v;
    }
    // 8 threads (consecutive lanes) share a row -> butterfly over cg bits
    ss += __shfl_xor_sync(0xffffffffu, ss, 1);
    ss += __shfl_xor_sync(0xffffffffu, ss, 2);
    ss += __shfl_xor_sync(0xffffffffu, ss, 4);
    float sc = 1.0f / fmaxf(sqrtf(ss), 1e-12f);

    int row = base + rw;
    if (row < N_NODES) {
        #pragma unroll
        for (int q = 0; q < 4; q++) {
            out4[row * 32 + cg * 4 + q] =
                make_float4(o[4*q] * sc, o[4*q+1] * sc, o[4*q+2] * sc, o[4*q+3] * sc);
        }
    }
}

// ---------------------------------------------------------------------------
extern "C" void kernel_launch(void* const* d_in, const int* in_sizes, int n_in,
                              void* d_out, int out_size) {
    const float4*    x4   = (const float4*)d_in[0];
    const long long* ei   = (const long long*)d_in[1];
    const float4*    W4   = (const float4*)d_in[2];
    const float*     bias = (const float*)d_in[3];
    float4*          out4 = (float4*)d_out;

    const int smem_bytes = (8192 + 32 * 65) * 16;  // 164352
    cudaFuncSetAttribute(gemm_norm_kernel,
                         cudaFuncAttributeMaxDynamicSharedMemorySize, smem_bytes);

    // 1) zero scratch + dtype probe
    zero_kernel<<<(N_NODES * 32 + 255) / 256, 256>>>(ei);
    // 2) edge scatter: one warp per edge
    scatter_kernel<<<(N_EDGES * 32) / 256, 256>>>(x4, ei);
    // 3) fused GEMM + bias + L2 normalize
    gemm_norm_kernel<<<(N_NODES + 31) / 32, 256, smem_bytes>>>(x4, W4, bias, out4);
}

// round 3
// speedup vs baseline: 1.2227x; 1.2227x over previous
#include <cuda_runtime.h>
#include <cstdint>

#define N_NODES 50000
#define N_EDGES 800000
#define SCAN_BLOCKS ((N_NODES + 255) / 256)   // 196

// ---- scratch (device globals; no allocs) ----
__device__ __align__(16) float4 g_neigh4[N_NODES * 32];   // mean-aggregated neigh
__device__ int g_deg_i[N_NODES];     // in-degree counts
__device__ int g_part[N_NODES];      // per-block exclusive prefix
__device__ int g_bsum[256];          // block sums (196 used)
__device__ int g_cursor[N_NODES];    // bin cursors (== end offsets after fill)
__device__ int g_src_bin[N_EDGES];   // src ids sorted by dst
__device__ int g_ei_is64;            // edge_index dtype flag

// ---- helpers: dtype-agnostic edge index reads ----
__device__ __forceinline__ int load_src(const long long* ei, int e) {
    return g_ei_is64 ? (int)__ldg(ei + e) : __ldg(((const int*)ei) + e);
}
__device__ __forceinline__ int load_dst(const long long* ei, int e) {
    return g_ei_is64 ? (int)__ldg(ei + N_EDGES + e) : __ldg(((const int*)ei) + N_EDGES + e);
}

// ---------------------------------------------------------------------------
// K1: zero degree counters + probe edge_index dtype
// ---------------------------------------------------------------------------
__global__ void __launch_bounds__(256) k_zero(const long long* __restrict__ ei) {
    int i = blockIdx.x * blockDim.x + threadIdx.x;
    if (i < N_NODES) g_deg_i[i] = 0;
    if (i == 0) {
        int ok = 1;
        for (int k = 0; k < 64; k++) {
            long long v = ei[k];
            if (v < 0 || v >= N_NODES) { ok = 0; break; }
        }
        g_ei_is64 = ok;
    }
}

// ---------------------------------------------------------------------------
// K2: in-degree histogram (int RED, no return)
// ---------------------------------------------------------------------------
__global__ void __launch_bounds__(256) k_hist(const long long* __restrict__ ei) {
    int e = blockIdx.x * blockDim.x + threadIdx.x;
    if (e >= N_EDGES) return;
    int d = load_dst(ei, e);
    if ((unsigned)d < N_NODES) atomicAdd(&g_deg_i[d], 1);
}

// ---------------------------------------------------------------------------
// K3a: per-block exclusive scan of degrees (256/block), emit block sums
// ---------------------------------------------------------------------------
__global__ void __launch_bounds__(256) k_scan1() {
    __shared__ int s[256];
    int i = blockIdx.x * 256 + threadIdx.x;
    int v = (i < N_NODES) ? g_deg_i[i] : 0;
    s[threadIdx.x] = v;
    __syncthreads();
    int acc = v;
    #pragma unroll
    for (int off = 1; off < 256; off <<= 1) {
        int t = (threadIdx.x >= off) ? s[threadIdx.x - off] : 0;
        __syncthreads();
        acc += t;
        s[threadIdx.x] = acc;
        __syncthreads();
    }
    if (i < N_NODES) g_part[i] = acc - v;          // exclusive
    if (threadIdx.x == 255) g_bsum[blockIdx.x] = acc;  // block total
}

// K3b: exclusive scan of the 196 block sums (single block)
__global__ void __launch_bounds__(256) k_scan2() {
    __shared__ int s[256];
    int v = (threadIdx.x < SCAN_BLOCKS) ? g_bsum[threadIdx.x] : 0;
    s[threadIdx.x] = v;
    __syncthreads();
    int acc = v;
    #pragma unroll
    for (int off = 1; off < 256; off <<= 1) {
        int t = (threadIdx.x >= off) ? s[threadIdx.x - off] : 0;
        __syncthreads();
        acc += t;
        s[threadIdx.x] = acc;
        __syncthreads();
    }
    if (threadIdx.x < SCAN_BLOCKS) g_bsum[threadIdx.x] = acc - v;  // exclusive
}

// K3c: global offsets -> cursors
__global__ void __launch_bounds__(256) k_scan3() {
    int i = blockIdx.x * 256 + threadIdx.x;
    if (i < N_NODES) g_cursor[i] = g_part[i] + g_bsum[blockIdx.x];
}

// ---------------------------------------------------------------------------
// K4: bin fill — counting-sort src ids by dst
// ---------------------------------------------------------------------------
__global__ void __launch_bounds__(256) k_binfill(const long long* __restrict__ ei) {
    int e = blockIdx.x * blockDim.x + threadIdx.x;
    if (e >= N_EDGES) return;
    int s = load_src(ei, e);
    int d = load_dst(ei, e);
    if ((unsigned)s >= N_NODES || (unsigned)d >= N_NODES) return;
    int pos = atomicAdd(&g_cursor[d], 1);
    g_src_bin[pos] = s;
}

// ---------------------------------------------------------------------------
// K5: gather-aggregate. One warp per node; lane = float4 channel chunk.
// Registers accumulate; single non-atomic write of the neighbor MEAN.
// ---------------------------------------------------------------------------
__global__ void __launch_bounds__(256) k_aggregate(const float4* __restrict__ x4) {
    int n = (blockIdx.x * blockDim.x + threadIdx.x) >> 5;
    int lane = threadIdx.x & 31;
    if (n >= N_NODES) return;

    int end = g_cursor[n];          // == off[n] + deg[n] after binfill
    int deg = g_deg_i[n];
    int beg = end - deg;

    float4 a0 = make_float4(0.f, 0.f, 0.f, 0.f);
    float4 a1 = make_float4(0.f, 0.f, 0.f, 0.f);

    for (int base = beg; base < end; base += 32) {
        int m = min(32, end - base);
        int s = (base + lane < end) ? __ldg(g_src_bin + base + lane) : 0;
        int j = 0;
        for (; j + 1 < m; j += 2) {           // 2-way unroll for MLP
            int s0 = __shfl_sync(0xffffffffu, s, j);
            int s1 = __shfl_sync(0xffffffffu, s, j + 1);
            float4 v0 = __ldg(x4 + s0 * 32 + lane);
            float4 v1 = __ldg(x4 + s1 * 32 + lane);
            a0.x += v0.x; a0.y += v0.y; a0.z += v0.z; a0.w += v0.w;
            a1.x += v1.x; a1.y += v1.y; a1.z += v1.z; a1.w += v1.w;
        }
        if (j < m) {
            int s0 = __shfl_sync(0xffffffffu, s, j);
            float4 v0 = __ldg(x4 + s0 * 32 + lane);
            a0.x += v0.x; a0.y += v0.y; a0.z += v0.z; a0.w += v0.w;
        }
    }
    float sc = 1.0f / fmaxf((float)deg, 1.0f);
    g_neigh4[n * 32 + lane] = make_float4((a0.x + a1.x) * sc, (a0.y + a1.y) * sc,
                                          (a0.z + a1.z) * sc, (a0.w + a1.w) * sc);
}

// ---------------------------------------------------------------------------
// K6: fused [x | neigh] @ W^T + b, row L2-normalize (neigh pre-scaled).
// ---------------------------------------------------------------------------
#define FMA2(acc, av, wv) \
    asm("fma.rn.f32x2 %0, %1, %2, %0;" : "+l"(acc) : "l"(av), "l"(wv))
#define UNPACK2(lo, hi, v) \
    asm("mov.b64 {%0,%1}, %2;" : "=f"(lo), "=f"(hi) : "l"(v))

__global__ void __launch_bounds__(256, 1) gemm_norm_kernel(
    const float4* __restrict__ x4,
    const float4* __restrict__ W4,     // [128][64] float4 (W[c][k])
    const float*  __restrict__ bias,   // [128]
    float4*       __restrict__ out4)   // [N_NODES][32]
{
    extern __shared__ float4 sm[];
    float4* Ws = sm;            // 8192 float4, XOR-swizzled
    float4* hs = sm + 8192;     // [32 rows][65] padded

    const int tid  = threadIdx.x;
    const int base = blockIdx.x * 32;

    #pragma unroll
    for (int i = tid; i < 8192; i += 256) {
        int c = i >> 6, ch = i & 63;
        Ws[(c << 6) | (ch ^ (c >> 4))] = __ldg(W4 + i);
    }
    #pragma unroll
    for (int i = tid; i < 2048; i += 256) {
        int r = i >> 6, k4 = i & 63;
        int row = base + r;
        float4 v = make_float4(0.f, 0.f, 0.f, 0.f);
        if (row < N_NODES)
            v = (k4 < 32) ? __ldg(x4 + row * 32 + k4)
                          : g_neigh4[row * 32 + (k4 - 32)];
        hs[r * 65 + k4] = v;
    }
    __syncthreads();

    const int cg = tid & 7;
    const int rw = tid >> 3;

    unsigned long long accA[16], accB[16];
    #pragma unroll
    for (int j = 0; j < 16; j++) { accA[j] = 0ull; accB[j] = 0ull; }

    const ulonglong2* WsU = (const ulonglong2*)Ws;
    const ulonglong2* hsU = (const ulonglong2*)hs;

    #pragma unroll 4
    for (int k4 = 0; k4 < 64; ++k4) {
        ulonglong2 a = hsU[rw * 65 + k4];
        int wbase = (cg << 10) | (k4 ^ cg);
        #pragma unroll
        for (int j = 0; j < 16; j++) {
            ulonglong2 w = WsU[wbase + (j << 6)];
            FMA2(accA[j], a.x, w.x);
            FMA2(accB[j], a.y, w.y);
        }
    }

    float o[16];
    float ss = 0.f;
    #pragma unroll
    for (int j = 0; j < 16; j++) {
        float x0, x1, y0, y1;
        UNPACK2(x0, x1, accA[j]);
        UNPACK2(y0, y1, accB[j]);
        float v = (x0 + x1) + (y0 + y1) + __ldg(bias + cg * 16 + j);
        o[j] = v;
        ss += v * v;
    }
    ss += __shfl_xor_sync(0xffffffffu, ss, 1);
    ss += __shfl_xor_sync(0xffffffffu, ss, 2);
    ss += __shfl_xor_sync(0xffffffffu, ss, 4);
    float sc = 1.0f / fmaxf(sqrtf(ss), 1e-12f);

    int row = base + rw;
    if (row < N_NODES) {
        #pragma unroll
        for (int q = 0; q < 4; q++) {
            out4[row * 32 + cg * 4 + q] =
                make_float4(o[4*q] * sc, o[4*q+1] * sc, o[4*q+2] * sc, o[4*q+3] * sc);
        }
    }
}

// ---------------------------------------------------------------------------
extern "C" void kernel_launch(void* const* d_in, const int* in_sizes, int n_in,
                              void* d_out, int out_size) {
    const float4*    x4   = (const float4*)d_in[0];
    const long long* ei   = (const long long*)d_in[1];
    const float4*    W4   = (const float4*)d_in[2];
    const float*     bias = (const float*)d_in[3];
    float4*          out4 = (float4*)d_out;

    const int smem_bytes = (8192 + 32 * 65) * 16;  // 164352
    cudaFuncSetAttribute(gemm_norm_kernel,
                         cudaFuncAttributeMaxDynamicSharedMemorySize, smem_bytes);

    const int EB = (N_EDGES + 255) / 256;   // 3125

    k_zero<<<SCAN_BLOCKS, 256>>>(ei);
    k_hist<<<EB, 256>>>(ei);
    k_scan1<<<SCAN_BLOCKS, 256>>>();
    k_scan2<<<1, 256>>>();
    k_scan3<<<SCAN_BLOCKS, 256>>>();
    k_binfill<<<EB, 256>>>(ei);
    k_aggregate<<<(N_NODES * 32 + 255) / 256, 256>>>(x4);
    gemm_norm_kernel<<<(N_NODES + 31) / 32, 256, smem_bytes>>>(x4, W4, bias, out4);
}